// round 3
// baseline (speedup 1.0000x reference)
#include <cuda_runtime.h>

typedef unsigned long long u64;

// Scratch (device globals; no allocations allowed).
__device__ __align__(16) float g_Gp[4 * 8 * 65536];   // gram partials (K-split 4)
__device__ __align__(16) float g_G [8 * 65536];       // G[b*4+q] 256x256
__device__ __align__(16) float g_T [8 * 1024 * 256];  // T[b*4+a] 1024x256
__device__ __align__(16) float g_Mp[2 * 8 * 65536];   // fold partials (K-split 2)
__device__ __align__(16) float g_M [8 * 65536];       // M[b*4+a] 256x256

__device__ __forceinline__ u64 fma2(u64 a, u64 b, u64 c) {
    u64 d;
    asm("fma.rn.f32x2 %0, %1, %2, %3;" : "=l"(d) : "l"(a), "l"(b), "l"(c));
    return d;
}
__device__ __forceinline__ float lo_f(u64 v) { return __uint_as_float((unsigned)v); }
__device__ __forceinline__ float hi_f(u64 v) { return __uint_as_float((unsigned)(v >> 32)); }

// Tile config: 128x64 tile, BK=32, 256 threads, 8m x 4n micro-tile (m packed in pairs).
constexpr int BM = 128, BN = 64, BK = 32;
constexpr int SA = 132;  // As row stride (floats): 128 + 4 pad, 16B-aligned rows
constexpr int SB = 132;  // Bs row stride (floats): holds 2*64 duplicated + 4 pad

// C[m,n] += A(.)B where As[k][m], Bs_dup[k][2n]. TRANS_A: A global is [K x M]
// (read rows directly); else A is [M x K] (transpose into SMEM at fill).
template <bool TRANS_A>
__device__ __forceinline__ void gemm_core(
    const float* __restrict__ A, int lda,
    const float* __restrict__ B, int ldb,
    float* __restrict__ C, int ldc,
    int kbeg, int kend, int m0, int n0)
{
    __shared__ __align__(16) float As[BK * SA];
    __shared__ __align__(16) float Bs[BK * SB];

    const int tid = threadIdx.x;
    const int tx = tid & 15;      // n sub-tile (4 cols)
    const int ty = tid >> 4;      // m sub-tile (8 rows = 4 pairs)
    // loader indices
    const int a_c4 = tid & 7,  a_r  = tid >> 3;   // NN A: 8 float4 per 32-k row
    const int t_c4 = tid & 31, t_kr = tid >> 5;   // TN A: 32 float4 per 128-m row
    const int b_c4 = tid & 15, b_kr = tid >> 4;   // B  : 16 float4 per 64-n row

    u64 acc[4][4] = {};

    for (int k0 = kbeg; k0 < kend; k0 += BK) {
        if (TRANS_A) {
            #pragma unroll
            for (int p = 0; p < 4; p++) {
                int k = t_kr + p * 8;
                float4 v = *reinterpret_cast<const float4*>(
                    &A[(size_t)(k0 + k) * lda + m0 + t_c4 * 4]);
                *reinterpret_cast<float4*>(&As[k * SA + t_c4 * 4]) = v;
            }
        } else {
            #pragma unroll
            for (int p = 0; p < 4; p++) {
                int m = a_r + p * 32;
                float4 v = *reinterpret_cast<const float4*>(
                    &A[(size_t)(m0 + m) * lda + k0 + a_c4 * 4]);
                As[(a_c4 * 4 + 0) * SA + m] = v.x;
                As[(a_c4 * 4 + 1) * SA + m] = v.y;
                As[(a_c4 * 4 + 2) * SA + m] = v.z;
                As[(a_c4 * 4 + 3) * SA + m] = v.w;
            }
        }
        #pragma unroll
        for (int p = 0; p < 2; p++) {
            int k = b_kr + p * 16;
            float4 v = *reinterpret_cast<const float4*>(
                &B[(size_t)(k0 + k) * ldb + n0 + b_c4 * 4]);
            float2* d = reinterpret_cast<float2*>(&Bs[k * SB + b_c4 * 8]);
            d[0] = make_float2(v.x, v.x);
            d[1] = make_float2(v.y, v.y);
            d[2] = make_float2(v.z, v.z);
            d[3] = make_float2(v.w, v.w);
        }
        __syncthreads();

        #pragma unroll
        for (int kk = 0; kk < BK; kk++) {
            ulonglong2 av0 = *reinterpret_cast<const ulonglong2*>(&As[kk * SA + ty * 8]);
            ulonglong2 av1 = *reinterpret_cast<const ulonglong2*>(&As[kk * SA + ty * 8 + 4]);
            ulonglong2 bv0 = *reinterpret_cast<const ulonglong2*>(&Bs[kk * SB + tx * 8]);
            ulonglong2 bv1 = *reinterpret_cast<const ulonglong2*>(&Bs[kk * SB + tx * 8 + 4]);
            u64 a[4] = {av0.x, av0.y, av1.x, av1.y};
            u64 b[4] = {bv0.x, bv0.y, bv1.x, bv1.y};
            #pragma unroll
            for (int i = 0; i < 4; i++)
                #pragma unroll
                for (int j = 0; j < 4; j++)
                    acc[i][j] = fma2(a[i], b[j], acc[i][j]);
        }
        __syncthreads();
    }

    #pragma unroll
    for (int i = 0; i < 4; i++) {
        int mrow = m0 + ty * 8 + 2 * i;
        float4 o0, o1;
        o0.x = lo_f(acc[i][0]); o0.y = lo_f(acc[i][1]);
        o0.z = lo_f(acc[i][2]); o0.w = lo_f(acc[i][3]);
        o1.x = hi_f(acc[i][0]); o1.y = hi_f(acc[i][1]);
        o1.z = hi_f(acc[i][2]); o1.w = hi_f(acc[i][3]);
        *reinterpret_cast<float4*>(&C[(size_t)mrow * ldc + n0 + tx * 4]) = o0;
        *reinterpret_cast<float4*>(&C[(size_t)(mrow + 1) * ldc + n0 + tx * 4]) = o1;
    }
}

// Stage A: G[b,q] = X^T X, X = hidden[b, :, q*256:(q+1)*256]  (K=2048, split 4)
// grid (8, 8, 4): 2x4 tiles of 256x256, 8 (b,q) pairs, 4 K-splits
__global__ void __launch_bounds__(256) k_gram(const float* __restrict__ hidden)
{
    const int pair = blockIdx.y;                  // b*4 + q
    const int b = pair >> 2, q = pair & 3;
    const float* X = hidden + (size_t)b * 2048 * 1024 + q * 256;
    float* C = g_Gp + ((size_t)blockIdx.z * 8 + pair) * 65536;
    const int m0 = (blockIdx.x >> 2) * BM, n0 = (blockIdx.x & 3) * BN;
    const int kbeg = blockIdx.z * 512;
    gemm_core<true>(X, 1024, X, 1024, C, 256, kbeg, kbeg + 512, m0, n0);
}

__global__ void __launch_bounds__(256) k_gred()
{
    const int i = blockIdx.x * 256 + threadIdx.x;     // 131072 float4 total
    const float4* P = reinterpret_cast<const float4*>(g_Gp);
    float4 s = P[i];
    float4 t1 = P[i + 131072], t2 = P[i + 2 * 131072], t3 = P[i + 3 * 131072];
    s.x += t1.x + t2.x + t3.x;
    s.y += t1.y + t2.y + t3.y;
    s.z += t1.z + t2.z + t3.z;
    s.w += t1.w + t2.w + t3.w;
    reinterpret_cast<float4*>(g_G)[i] = s;
}

// Stage B1: T[b,a][q*256+f, g] = G[b,q] @ C_{a,q}   grid (8, 32)
__global__ void __launch_bounds__(256) k_gc(const float* __restrict__ comb)
{
    const int combo = blockIdx.y;                 // ((b*4+a)*4 + q)
    const int q = combo & 3, a = (combo >> 2) & 3, b = combo >> 4;
    const float* A = g_G + (size_t)(b * 4 + q) * 65536;
    const float* B = comb + ((size_t)a * 1024 + q * 256) * 256;
    float* C = g_T + ((size_t)(b * 4 + a) * 1024 + q * 256) * 256;
    const int m0 = (blockIdx.x >> 2) * BM, n0 = (blockIdx.x & 3) * BN;
    gemm_core<false>(A, 256, B, 256, C, 256, 0, 256, m0, n0);
}

// Stage B2: M[b,a] = queries[a] (256x1024) @ T[b,a] (1024x256)  (K split 2)
// grid (8, 8, 2)
__global__ void __launch_bounds__(256) k_fold(const float* __restrict__ queries)
{
    const int combo = blockIdx.y;                 // b*4 + a
    const int a = combo & 3;
    const float* A = queries + (size_t)a * 256 * 1024;
    const float* B = g_T + (size_t)combo * 1024 * 256;
    float* C = g_Mp + ((size_t)blockIdx.z * 8 + combo) * 65536;
    const int m0 = (blockIdx.x >> 2) * BM, n0 = (blockIdx.x & 3) * BN;
    const int kbeg = blockIdx.z * 512;
    gemm_core<false>(A, 1024, B, 256, C, 256, kbeg, kbeg + 512, m0, n0);
}

__global__ void __launch_bounds__(256) k_mred()
{
    const int i = blockIdx.x * 256 + threadIdx.x;     // 131072 float4 total
    const float4* P = reinterpret_cast<const float4*>(g_Mp);
    float4 s = P[i];
    float4 t1 = P[i + 131072];
    s.x += t1.x; s.y += t1.y; s.z += t1.z; s.w += t1.w;
    reinterpret_cast<float4*>(g_M)[i] = s;
}

// Stage C: out[b, :, a*256:(a+1)*256] = hidden[b, :, a*256:(a+1)*256] @ M[b,a]
// grid (64, 8): 16x4 tiles of 2048x256, 8 (b,a) pairs
__global__ void __launch_bounds__(256) k_out(const float* __restrict__ hidden,
                                             float* __restrict__ out)
{
    const int combo = blockIdx.y;                 // b*4 + a
    const int b = combo >> 2, a = combo & 3;
    const float* A = hidden + (size_t)b * 2048 * 1024 + a * 256;
    const float* B = g_M + (size_t)combo * 65536;
    float* C = out + (size_t)b * 2048 * 1024 + a * 256;
    const int m0 = (blockIdx.x >> 2) * BM, n0 = (blockIdx.x & 3) * BN;
    gemm_core<false>(A, 1024, B, 256, C, 1024, 0, 256, m0, n0);
}

extern "C" void kernel_launch(void* const* d_in, const int* in_sizes, int n_in,
                              void* d_out, int out_size)
{
    const float* hidden  = (const float*)d_in[0];   // [2, 2048, 1024]
    const float* queries = (const float*)d_in[1];   // [4, 256, 1024]
    const float* comb    = (const float*)d_in[2];   // [4, 1024, 256]
    float* out = (float*)d_out;                     // [2, 2048, 1024]

    dim3 blk(256);
    k_gram<<<dim3(8, 8, 4), blk>>>(hidden);
    k_gred<<<512, 256>>>();
    k_gc  <<<dim3(8, 32), blk>>>(comb);
    k_fold<<<dim3(8, 8, 2), blk>>>(queries);
    k_mred<<<512, 256>>>();
    k_out <<<dim3(64, 8), blk>>>(hidden, out);
}